// round 9
// baseline (speedup 1.0000x reference)
#include <cuda_runtime.h>
#include <math.h>

#define NMAX   20480
#define KNN    16
#define HDIM   256
#define SAMPLE 8192
#define SUBW   16
#define THTILE 2048                // smem tile for phase A (32KB)
#define THHALF 4096                // per-y-slice sample range
#define KTB    1024
#define CSPB   8                   // phase-B candidate split
#define CAP    1024                // survivor capacity per query

typedef unsigned long long u64;

#define FMA2(d, a, b, c) asm("fma.rn.f32x2 %0, %1, %2, %3;" : "=l"(d) : "l"(a), "l"(b), "l"(c))
#define UNPACK2(lo, hi, in) asm("mov.b64 {%0, %1}, %2;" : "=r"(lo), "=r"(hi) : "l"(in))

// ---------------- scratch (no allocations allowed) ----------------
__device__ float4 g_c4[NMAX];
__device__ float  g_thd[2 * NMAX * KNN];        // per-half sorted sub-minima top-16
__device__ float  g_thr[NMAX];
__device__ int    g_scnt[NMAX];
__device__ int2   g_surv[(size_t)NMAX * CAP];   // (dist bits, idx)
__device__ int    g_idx[NMAX * KNN];
__device__ int    g_deg[NMAX];
__device__ float  g_srcnorm[NMAX];
__device__ float  g_bufA[NMAX * HDIM];
__device__ float  g_bufB[NMAX * HDIM];
__device__ float  g_bufC[NMAX * HDIM];

__device__ __forceinline__ float* bufptr(int s) {
    return s == 0 ? g_bufA : (s == 1 ? g_bufB : g_bufC);
}

// ---------------- pack centers into float4 (x,y,z,|c|^2), zero degrees/counters --------
__global__ void pack_kernel(const float* __restrict__ centers, int N) {
    int i = blockIdx.x * blockDim.x + threadIdx.x;
    if (i < N) {
        float x = centers[3 * i + 0];
        float y = centers[3 * i + 1];
        float z = centers[3 * i + 2];
        g_c4[i] = make_float4(x, y, z, x * x + y * y + z * z);
        g_deg[i] = 0;
        g_scnt[i] = 0;
    }
}

// ---------------- Phase A: sub-minima top-16 over a sample half (blockIdx.y) -----------
// Disjoint width-16 sub-blocks: the 16 smallest sub-minima (merged over both halves)
// are 16 distinct candidates all <= t, hence t >= true 16th-NN distance.
__global__ void knn_thresh_kernel(int N) {
    __shared__ float4 sc[THTILE];
    int q = blockIdx.x * blockDim.x + threadIdx.x;
    int y = blockIdx.y;
    int send = min(N, SAMPLE);
    int c0 = y * THHALF;
    int c1 = min(send, c0 + THHALF);

    float nx = 0.f, ny = 0.f, nz = 0.f;
    if (q < N) {
        float4 p = g_c4[q];
        nx = -2.f * p.x; ny = -2.f * p.y; nz = -2.f * p.z;
    }
    float bd[KNN];
#pragma unroll
    for (int k = 0; k < KNN; k++) bd[k] = 3.4e38f;

    for (int base = c0; base < c1; base += THTILE) {
        int cnt = min(THTILE, c1 - base);
        __syncthreads();
        for (int t = threadIdx.x; t < cnt; t += blockDim.x) sc[t] = g_c4[base + t];
        __syncthreads();
        if (q < N) {
            int nsub = cnt / SUBW;
            for (int b = 0; b < nsub; b++) {
                float m0 = 3.4e38f, m1 = 3.4e38f;
#pragma unroll
                for (int j = 0; j < SUBW; j++) {
                    float4 v = sc[b * SUBW + j];
                    float d = fmaf(v.x, nx, fmaf(v.y, ny, fmaf(v.z, nz, v.w)));
                    if (j & 1) m1 = fminf(m1, d); else m0 = fminf(m0, d);
                }
                float cd = fminf(m0, m1);
                if (cd < bd[KNN - 1]) {
#pragma unroll
                    for (int k = 0; k < KNN; k++) {
                        float lo = fminf(cd, bd[k]);
                        float hi = fmaxf(cd, bd[k]);
                        bd[k] = lo; cd = hi;
                    }
                }
            }
        }
    }
    if (q < N) {
#pragma unroll
        for (int k = 0; k < KNN; k++) g_thd[(y * N + q) * KNN + k] = bd[k];
    }
}

// ---------------- merge the two sorted sub-minima lists -> threshold ----------
__global__ void thr_merge_kernel(int N) {
    int q = blockIdx.x * blockDim.x + threadIdx.x;
    if (q >= N) return;
    const float* A = &g_thd[(size_t)q * KNN];
    const float* B = &g_thd[((size_t)N + q) * KNN];
    int pa = 0, pb = 0;
    float v = 3.4e38f;
#pragma unroll
    for (int k = 0; k < KNN; k++) {
        float va = __ldg(&A[pa]);
        float vb = __ldg(&B[pb]);
        if (va <= vb) { v = va; pa++; } else { v = vb; pb++; }
    }
    g_thr[q] = v;
}

// ---------------- Phase B: filtered full scan, append survivors ----------------
__global__ void knn_filter_kernel(int N) {
    __shared__ float4 sc[KTB];
    int half = (N + 1) >> 1;
    int t0i = blockIdx.x * blockDim.x + threadIdx.x;
    int q0 = t0i;
    int q1 = t0i + half;
    bool v0 = (q0 < N);
    bool v1 = (q1 < N);

    int chunk = (N + CSPB - 1) / CSPB;
    int c0 = blockIdx.y * chunk;
    int c1 = min(N, c0 + chunk);

    float nx0 = 0.f, ny0 = 0.f, nz0 = 0.f, th0 = -3.4e38f;
    float nx1 = 0.f, ny1 = 0.f, nz1 = 0.f, th1 = -3.4e38f;
    if (v0) {
        float4 p = g_c4[q0];
        nx0 = -2.f * p.x; ny0 = -2.f * p.y; nz0 = -2.f * p.z;
        th0 = g_thr[q0];
    }
    if (v1) {
        float4 p = g_c4[q1];
        nx1 = -2.f * p.x; ny1 = -2.f * p.y; nz1 = -2.f * p.z;
        th1 = g_thr[q1];
    }

    for (int base = c0; base < c1; base += KTB) {
        int cnt = min(KTB, c1 - base);
        __syncthreads();
        for (int t = threadIdx.x; t < cnt; t += blockDim.x) sc[t] = g_c4[base + t];
        __syncthreads();
#pragma unroll 4
        for (int t = 0; t < cnt; t++) {
            float4 v = sc[t];
            float d0 = fmaf(v.x, nx0, fmaf(v.y, ny0, fmaf(v.z, nz0, v.w)));
            float d1 = fmaf(v.x, nx1, fmaf(v.y, ny1, fmaf(v.z, nz1, v.w)));
            if (d0 <= th0) {
                int s = atomicAdd(&g_scnt[q0], 1);
                if (s < CAP) g_surv[(size_t)q0 * CAP + s] =
                    make_int2(__float_as_int(d0), base + t);
            }
            if (d1 <= th1) {
                int s = atomicAdd(&g_scnt[q1], 1);
                if (s < CAP) g_surv[(size_t)q1 * CAP + s] =
                    make_int2(__float_as_int(d1), base + t);
            }
        }
    }
}

// ---------------- Phase C: exact top-16, deterministic (d, idx) tie-break ---------------
__global__ void knn_select_kernel(int N) {
    __shared__ float sd[32][4][KNN];
    __shared__ int   si[32][4][KNN];
    int tid = threadIdx.x;
    int sub = tid & 3;
    int qi  = tid >> 2;                 // 0..31
    int q = blockIdx.x * 32 + qi;
    bool valid = (q < N);

    float bd[KNN];
    int   bi[KNN];
#pragma unroll
    for (int k = 0; k < KNN; k++) { bd[k] = 3.4e38f; bi[k] = 0x7fffffff; }

    if (valid) {
        int cnt = min(g_scnt[q], CAP);
        const int2* sv = &g_surv[(size_t)q * CAP];
        for (int s = sub; s < cnt; s += 4) {
            int2 e = __ldg(&sv[s]);
            float cd = __int_as_float(e.x);
            if (cd <= bd[KNN - 1]) {
                int ci = e.y;
#pragma unroll
                for (int k = 0; k < KNN; k++) {
                    bool lt = (cd < bd[k]) || (cd == bd[k] && ci < bi[k]);
                    float lo = fminf(cd, bd[k]);
                    float hi = fmaxf(cd, bd[k]);
                    int ni = lt ? ci : bi[k];
                    ci = lt ? bi[k] : ci;
                    bd[k] = lo; bi[k] = ni; cd = hi;
                }
            }
        }
    }
#pragma unroll
    for (int k = 0; k < KNN; k++) {
        sd[qi][sub][k] = bd[k];
        si[qi][sub][k] = bi[k];
    }
    __syncthreads();

    if (valid && sub == 0) {
        int p[4] = {0, 0, 0, 0};
#pragma unroll
        for (int k = 0; k < KNN; k++) {
            float best = 3.5e38f;
            int bidx = 0x7fffffff;
            int bl = 0;
#pragma unroll
            for (int l = 0; l < 4; l++) {
                float v = (p[l] < KNN) ? sd[qi][l][p[l]] : 3.5e38f;
                int ix = (p[l] < KNN) ? si[qi][l][p[l]] : 0x7fffffff;
                if (v < best || (v == best && ix < bidx)) { best = v; bidx = ix; bl = l; }
            }
            p[bl]++;
            g_idx[q * KNN + k] = bidx;
            atomicAdd(&g_deg[bidx], 1);
        }
    }
}

// ---------------- src_norm = rsqrt(max(out_deg,1)) ----------------
__global__ void norm_kernel(int N) {
    int i = blockIdx.x * blockDim.x + threadIdx.x;
    if (i < N) {
        float d = (float)g_deg[i];
        g_srcnorm[i] = rsqrtf(fmaxf(d, 1.f));
    }
}

// ---------------- neighbor aggregation: agg[i] = 0.25 * sum_k srcnorm[j]*h[j] ----------
__global__ void agg_kernel(const float* __restrict__ xin, int srcSel, int dstSel,
                           int F, int N) {
    const float* src = (srcSel < 0) ? xin : bufptr(srcSel);
    float* dst = bufptr(dstSel);
    int tpr = F >> 2;
    int rpb = blockDim.x / tpr;
    int r = threadIdx.x / tpr;
    int c = threadIdx.x % tpr;
    int node = blockIdx.x * rpb + r;
    if (node >= N) return;
    const float4* s4 = (const float4*)src;
    float4 acc = make_float4(0.f, 0.f, 0.f, 0.f);
    const int* ip = &g_idx[node * KNN];
#pragma unroll
    for (int k = 0; k < KNN; k++) {
        int j = __ldg(&ip[k]);
        float s = __ldg(&g_srcnorm[j]);
        float4 v = s4[j * tpr + c];
        acc.x = fmaf(s, v.x, acc.x);
        acc.y = fmaf(s, v.y, acc.y);
        acc.z = fmaf(s, v.z, acc.z);
        acc.w = fmaf(s, v.w, acc.w);
    }
    const float dn = 0.25f;
    ((float4*)dst)[node * tpr + c] =
        make_float4(acc.x * dn, acc.y * dn, acc.z * dn, acc.w * dn);
}

// ---------------- fp32 GEMM: f32x2 FFMA, duplicated-A smem, double-buffered ------------
// BM=128, BN=128, BK=8, 256 threads, 8x8 micro-tile as 8x4 f32x2 pairs
__global__ void gemm_kernel(int srcSel, const float* __restrict__ W,
                            const float* __restrict__ bias, int dstSel,
                            int M, int Kd) {
    const float* A = bufptr(srcSel);
    float* C = bufptr(dstSel);
    __shared__ float As2[2][8][276];   // [buf][k][2*row (+dup)] ; 276 = 256 + 20 pad
    __shared__ float Bs[2][8][128];    // [buf][k][col]
    int tid = threadIdx.x;
    int tx = tid & 15;
    int ty = tid >> 4;
    int bm0 = blockIdx.x * 128;
    int bn0 = blockIdx.y * 128;

    int arow = tid >> 1;               // 0..127
    int kq = (tid & 1) * 4;            // 0 or 4
    int grow = bm0 + arow;
    int brow = tid >> 5;               // 0..7
    int bc = (tid & 31) * 4;           // 0..124

    u64 acc2[8][4];
#pragma unroll
    for (int i = 0; i < 8; i++)
#pragma unroll
        for (int j = 0; j < 4; j++) acc2[i][j] = 0ull;

    int ktiles = Kd >> 3;

    // preload tile 0
    float4 av = make_float4(0.f, 0.f, 0.f, 0.f);
    if (grow < M) av = *(const float4*)&A[grow * Kd + kq];
    float4 bv = *(const float4*)&W[brow * HDIM + bn0 + bc];
    *(float2*)&As2[0][kq + 0][arow * 2] = make_float2(av.x, av.x);
    *(float2*)&As2[0][kq + 1][arow * 2] = make_float2(av.y, av.y);
    *(float2*)&As2[0][kq + 2][arow * 2] = make_float2(av.z, av.z);
    *(float2*)&As2[0][kq + 3][arow * 2] = make_float2(av.w, av.w);
    *(float4*)&Bs[0][brow][bc] = bv;
    __syncthreads();

    for (int kt = 0; kt < ktiles; kt++) {
        int buf = kt & 1;
        bool more = (kt + 1 < ktiles);
        if (more) {
            int k0 = (kt + 1) * 8;
            av = make_float4(0.f, 0.f, 0.f, 0.f);
            if (grow < M) av = *(const float4*)&A[grow * Kd + k0 + kq];
            bv = *(const float4*)&W[(k0 + brow) * HDIM + bn0 + bc];
        }
#pragma unroll
        for (int kk = 0; kk < 8; kk++) {
            const float* ar = &As2[buf][kk][ty * 16];
            ulonglong2 a01 = *(const ulonglong2*)(ar + 0);
            ulonglong2 a23 = *(const ulonglong2*)(ar + 4);
            ulonglong2 a45 = *(const ulonglong2*)(ar + 8);
            ulonglong2 a67 = *(const ulonglong2*)(ar + 12);
            u64 ap[8] = {a01.x, a01.y, a23.x, a23.y, a45.x, a45.y, a67.x, a67.y};
            ulonglong2 b01 = *(const ulonglong2*)&Bs[buf][kk][tx * 8];
            ulonglong2 b23 = *(const ulonglong2*)&Bs[buf][kk][tx * 8 + 4];
            u64 bp[4] = {b01.x, b01.y, b23.x, b23.y};
#pragma unroll
            for (int i = 0; i < 8; i++)
#pragma unroll
                for (int j = 0; j < 4; j++)
                    FMA2(acc2[i][j], ap[i], bp[j], acc2[i][j]);
        }
        if (more) {
            int nb = buf ^ 1;
            *(float2*)&As2[nb][kq + 0][arow * 2] = make_float2(av.x, av.x);
            *(float2*)&As2[nb][kq + 1][arow * 2] = make_float2(av.y, av.y);
            *(float2*)&As2[nb][kq + 2][arow * 2] = make_float2(av.z, av.z);
            *(float2*)&As2[nb][kq + 3][arow * 2] = make_float2(av.w, av.w);
            *(float4*)&Bs[nb][brow][bc] = bv;
        }
        __syncthreads();
    }

    float bb[8];
#pragma unroll
    for (int j = 0; j < 8; j++) bb[j] = __ldg(&bias[bn0 + tx * 8 + j]);
#pragma unroll
    for (int i = 0; i < 8; i++) {
        int row = bm0 + ty * 8 + i;
        if (row < M) {
            float o[8];
#pragma unroll
            for (int j = 0; j < 4; j++) {
                unsigned int lo, hi;
                UNPACK2(lo, hi, acc2[i][j]);
                o[2 * j + 0] = fmaxf(__uint_as_float(lo) + bb[2 * j + 0], 0.f);
                o[2 * j + 1] = fmaxf(__uint_as_float(hi) + bb[2 * j + 1], 0.f);
            }
            *(float4*)&C[row * HDIM + bn0 + tx * 8 + 0] = make_float4(o[0], o[1], o[2], o[3]);
            *(float4*)&C[row * HDIM + bn0 + tx * 8 + 4] = make_float4(o[4], o[5], o[6], o[7]);
        }
    }
}

// ---------------- final: sigmoid(h @ Wf + bf), one warp per row ----------------
__global__ void final_kernel(int srcSel, const float* __restrict__ Wf,
                             const float* __restrict__ bf,
                             float* __restrict__ out, int N) {
    __shared__ float sw[HDIM];
    const float* h = bufptr(srcSel);
    for (int i = threadIdx.x; i < HDIM; i += blockDim.x) sw[i] = Wf[i];
    __syncthreads();
    int warp = threadIdx.x >> 5;
    int lane = threadIdx.x & 31;
    int row = blockIdx.x * 8 + warp;
    if (row >= N) return;
    const float4* h4 = (const float4*)&h[row * HDIM];
    float4 v0 = h4[lane * 2 + 0];
    float4 v1 = h4[lane * 2 + 1];
    float4 w0 = *(const float4*)&sw[lane * 8 + 0];
    float4 w1 = *(const float4*)&sw[lane * 8 + 4];
    float s = v0.x * w0.x + v0.y * w0.y + v0.z * w0.z + v0.w * w0.w
            + v1.x * w1.x + v1.y * w1.y + v1.z * w1.z + v1.w * w1.w;
#pragma unroll
    for (int o = 16; o > 0; o >>= 1) s += __shfl_xor_sync(0xffffffffu, s, o);
    if (lane == 0) {
        float z = s + bf[0];
        out[row] = 1.f / (1.f + expf(-z));
    }
}

// ---------------- launch ----------------
extern "C" void kernel_launch(void* const* d_in, const int* in_sizes, int n_in,
                              void* d_out, int out_size) {
    const float* x       = (const float*)d_in[0];
    const float* centers = (const float*)d_in[1];
    const float* W0      = (const float*)d_in[2];
    const float* b0      = (const float*)d_in[3];
    const float* W1      = (const float*)d_in[4];
    const float* b1      = (const float*)d_in[5];
    const float* W2      = (const float*)d_in[6];
    const float* b2      = (const float*)d_in[7];
    const float* Wf      = (const float*)d_in[8];
    const float* bf      = (const float*)d_in[9];
    float* out = (float*)d_out;

    int N = in_sizes[1] / 3;           // 20000
    int D = in_sizes[0] / N;           // 128

    pack_kernel<<<(N + 255) / 256, 256>>>(centers, N);
    {
        dim3 tg((N + 127) / 128, 2);
        knn_thresh_kernel<<<tg, 128>>>(N);
    }
    thr_merge_kernel<<<(N + 255) / 256, 256>>>(N);
    {
        int half = (N + 1) / 2;
        dim3 kg((half + 127) / 128, CSPB);
        knn_filter_kernel<<<kg, 128>>>(N);
    }
    knn_select_kernel<<<(N + 31) / 32, 128>>>(N);
    norm_kernel<<<(N + 255) / 256, 256>>>(N);

    dim3 gg((N + 127) / 128, HDIM / 128);

    {
        int tpr = D / 4, rpb = 256 / tpr;
        agg_kernel<<<(N + rpb - 1) / rpb, 256>>>(x, -1, 0, D, N);
    }
    gemm_kernel<<<gg, 256>>>(0, W0, b0, 1, N, D);

    {
        int tpr = HDIM / 4, rpb = 256 / tpr;
        agg_kernel<<<(N + rpb - 1) / rpb, 256>>>(nullptr, 1, 0, HDIM, N);
    }
    gemm_kernel<<<gg, 256>>>(0, W1, b1, 2, N, HDIM);

    {
        int tpr = HDIM / 4, rpb = 256 / tpr;
        agg_kernel<<<(N + rpb - 1) / rpb, 256>>>(nullptr, 2, 0, HDIM, N);
    }
    gemm_kernel<<<gg, 256>>>(0, W2, b2, 1, N, HDIM);

    final_kernel<<<(N + 7) / 8, 256>>>(1, Wf, bf, out, N);
}

// round 10
// speedup vs baseline: 1.4863x; 1.4863x over previous
#include <cuda_runtime.h>
#include <math.h>

#define NMAX   20480
#define KNN    16
#define HDIM   256
#define SAMPLE 8192
#define SUBW   16
#define THTILE 2048                // smem tile for phase A (32KB)
#define THHALF 4096                // per-y-slice sample range
#define KTB    1024
#define CSPB   16                  // phase-B candidate split
#define CAP    1024                // survivor capacity per query

typedef unsigned long long u64;

#define PACK2(d, a) asm("mov.b64 %0, {%1, %2};" : "=l"(d) : "r"(__float_as_uint(a)), "r"(__float_as_uint(a)))
#define FMA2(d, a, b, c) asm("fma.rn.f32x2 %0, %1, %2, %3;" : "=l"(d) : "l"(a), "l"(b), "l"(c))
#define UNPACK2(lo, hi, in) asm("mov.b64 {%0, %1}, %2;" : "=r"(lo), "=r"(hi) : "l"(in))

// ---------------- scratch (no allocations allowed) ----------------
__device__ float4 g_c4[NMAX];
__device__ float  g_thd[2 * NMAX * KNN];        // per-half sorted sub-minima top-16
__device__ float  g_thr[NMAX];
__device__ int    g_scnt[NMAX];
__device__ int2   g_surv[(size_t)NMAX * CAP];   // (dist bits, idx)
__device__ int    g_idx[NMAX * KNN];
__device__ int    g_deg[NMAX];
__device__ float  g_srcnorm[NMAX];
__device__ float  g_bufA[NMAX * HDIM];
__device__ float  g_bufB[NMAX * HDIM];
__device__ float  g_bufC[NMAX * HDIM];

__device__ __forceinline__ float* bufptr(int s) {
    return s == 0 ? g_bufA : (s == 1 ? g_bufB : g_bufC);
}

// ---------------- pack centers into float4 (x,y,z,|c|^2), zero degrees/counters --------
__global__ void pack_kernel(const float* __restrict__ centers, int N) {
    int i = blockIdx.x * blockDim.x + threadIdx.x;
    if (i < N) {
        float x = centers[3 * i + 0];
        float y = centers[3 * i + 1];
        float z = centers[3 * i + 2];
        g_c4[i] = make_float4(x, y, z, x * x + y * y + z * z);
        g_deg[i] = 0;
        g_scnt[i] = 0;
    }
}

// ---------------- Phase A: sub-minima top-16 over a sample half (blockIdx.y) -----------
// Disjoint width-16 sub-blocks: the 16 smallest sub-minima (merged over both halves)
// are 16 distinct candidates all <= t, hence t >= true 16th-NN distance.
__global__ void knn_thresh_kernel(int N) {
    __shared__ float4 sc[THTILE];
    int q = blockIdx.x * blockDim.x + threadIdx.x;
    int y = blockIdx.y;
    int send = min(N, SAMPLE);
    int c0 = y * THHALF;
    int c1 = min(send, c0 + THHALF);

    float nx = 0.f, ny = 0.f, nz = 0.f;
    if (q < N) {
        float4 p = g_c4[q];
        nx = -2.f * p.x; ny = -2.f * p.y; nz = -2.f * p.z;
    }
    float bd[KNN];
#pragma unroll
    for (int k = 0; k < KNN; k++) bd[k] = 3.4e38f;

    for (int base = c0; base < c1; base += THTILE) {
        int cnt = min(THTILE, c1 - base);
        __syncthreads();
        for (int t = threadIdx.x; t < cnt; t += blockDim.x) sc[t] = g_c4[base + t];
        __syncthreads();
        if (q < N) {
            int nsub = cnt / SUBW;
            for (int b = 0; b < nsub; b++) {
                float m0 = 3.4e38f, m1 = 3.4e38f;
#pragma unroll
                for (int j = 0; j < SUBW; j++) {
                    float4 v = sc[b * SUBW + j];
                    float d = fmaf(v.x, nx, fmaf(v.y, ny, fmaf(v.z, nz, v.w)));
                    if (j & 1) m1 = fminf(m1, d); else m0 = fminf(m0, d);
                }
                float cd = fminf(m0, m1);
                if (cd < bd[KNN - 1]) {
#pragma unroll
                    for (int k = 0; k < KNN; k++) {
                        float lo = fminf(cd, bd[k]);
                        float hi = fmaxf(cd, bd[k]);
                        bd[k] = lo; cd = hi;
                    }
                }
            }
        }
    }
    if (q < N) {
#pragma unroll
        for (int k = 0; k < KNN; k++) g_thd[(y * N + q) * KNN + k] = bd[k];
    }
}

// ---------------- merge the two sorted sub-minima lists -> threshold ----------
__global__ void thr_merge_kernel(int N) {
    int q = blockIdx.x * blockDim.x + threadIdx.x;
    if (q >= N) return;
    const float* A = &g_thd[(size_t)q * KNN];
    const float* B = &g_thd[((size_t)N + q) * KNN];
    int pa = 0, pb = 0;
    float v = 3.4e38f;
#pragma unroll
    for (int k = 0; k < KNN; k++) {
        float va = __ldg(&A[pa]);
        float vb = __ldg(&B[pb]);
        if (va <= vb) { v = va; pa++; } else { v = vb; pb++; }
    }
    g_thr[q] = v;
}

// ---------------- Phase B: filtered full scan, append survivors ----------------
// q0 covers [0, half), q1 covers [half, N): each query scanned by EXACTLY one thread
// per candidate chunk (the q0<N bug double-scanned queries [half, half+pad) before).
__global__ void knn_filter_kernel(int N) {
    __shared__ float4 sc[KTB];
    int half = (N + 1) >> 1;
    int t0i = blockIdx.x * blockDim.x + threadIdx.x;
    int q0 = t0i;
    int q1 = t0i + half;
    bool v0 = (q0 < half);
    bool v1 = (q1 < N);

    int chunk = (N + CSPB - 1) / CSPB;
    int c0 = blockIdx.y * chunk;
    int c1 = min(N, c0 + chunk);

    float nx0 = 0.f, ny0 = 0.f, nz0 = 0.f, th0 = -3.4e38f;
    float nx1 = 0.f, ny1 = 0.f, nz1 = 0.f, th1 = -3.4e38f;
    if (v0) {
        float4 p = g_c4[q0];
        nx0 = -2.f * p.x; ny0 = -2.f * p.y; nz0 = -2.f * p.z;
        th0 = g_thr[q0];
    }
    if (v1) {
        float4 p = g_c4[q1];
        nx1 = -2.f * p.x; ny1 = -2.f * p.y; nz1 = -2.f * p.z;
        th1 = g_thr[q1];
    }

    for (int base = c0; base < c1; base += KTB) {
        int cnt = min(KTB, c1 - base);
        __syncthreads();
        for (int t = threadIdx.x; t < cnt; t += blockDim.x) sc[t] = g_c4[base + t];
        __syncthreads();
#pragma unroll 8
        for (int t = 0; t < cnt; t++) {
            float4 v = sc[t];
            float d0 = fmaf(v.x, nx0, fmaf(v.y, ny0, fmaf(v.z, nz0, v.w)));
            float d1 = fmaf(v.x, nx1, fmaf(v.y, ny1, fmaf(v.z, nz1, v.w)));
            // single rare branch; (d - th) is exact for nearby values (Sterbenz),
            // and th = -3.4e38 for invalid queries never triggers.
            if (fminf(d0 - th0, d1 - th1) <= 0.f) {
                if (d0 <= th0) {
                    int s = atomicAdd(&g_scnt[q0], 1);
                    if (s < CAP) g_surv[(size_t)q0 * CAP + s] =
                        make_int2(__float_as_int(d0), base + t);
                }
                if (d1 <= th1) {
                    int s = atomicAdd(&g_scnt[q1], 1);
                    if (s < CAP) g_surv[(size_t)q1 * CAP + s] =
                        make_int2(__float_as_int(d1), base + t);
                }
            }
        }
    }
}

// ---------------- Phase C: exact top-16, deterministic (d, idx) tie-break ---------------
__global__ void knn_select_kernel(int N) {
    __shared__ float sd[32][4][KNN];
    __shared__ int   si[32][4][KNN];
    int tid = threadIdx.x;
    int sub = tid & 3;
    int qi  = tid >> 2;                 // 0..31
    int q = blockIdx.x * 32 + qi;
    bool valid = (q < N);

    float bd[KNN];
    int   bi[KNN];
#pragma unroll
    for (int k = 0; k < KNN; k++) { bd[k] = 3.4e38f; bi[k] = 0x7fffffff; }

    if (valid) {
        int cnt = min(g_scnt[q], CAP);
        const int2* sv = &g_surv[(size_t)q * CAP];
        for (int s = sub; s < cnt; s += 4) {
            int2 e = __ldg(&sv[s]);
            float cd = __int_as_float(e.x);
            if (cd <= bd[KNN - 1]) {
                int ci = e.y;
#pragma unroll
                for (int k = 0; k < KNN; k++) {
                    bool lt = (cd < bd[k]) || (cd == bd[k] && ci < bi[k]);
                    float lo = fminf(cd, bd[k]);
                    float hi = fmaxf(cd, bd[k]);
                    int ni = lt ? ci : bi[k];
                    ci = lt ? bi[k] : ci;
                    bd[k] = lo; bi[k] = ni; cd = hi;
                }
            }
        }
    }
#pragma unroll
    for (int k = 0; k < KNN; k++) {
        sd[qi][sub][k] = bd[k];
        si[qi][sub][k] = bi[k];
    }
    __syncthreads();

    if (valid && sub == 0) {
        int p[4] = {0, 0, 0, 0};
#pragma unroll
        for (int k = 0; k < KNN; k++) {
            float best = 3.5e38f;
            int bidx = 0x7fffffff;
            int bl = 0;
#pragma unroll
            for (int l = 0; l < 4; l++) {
                float v = (p[l] < KNN) ? sd[qi][l][p[l]] : 3.5e38f;
                int ix = (p[l] < KNN) ? si[qi][l][p[l]] : 0x7fffffff;
                if (v < best || (v == best && ix < bidx)) { best = v; bidx = ix; bl = l; }
            }
            p[bl]++;
            g_idx[q * KNN + k] = bidx;
            atomicAdd(&g_deg[bidx], 1);
        }
    }
}

// ---------------- src_norm = rsqrt(max(out_deg,1)) ----------------
__global__ void norm_kernel(int N) {
    int i = blockIdx.x * blockDim.x + threadIdx.x;
    if (i < N) {
        float d = (float)g_deg[i];
        g_srcnorm[i] = rsqrtf(fmaxf(d, 1.f));
    }
}

// ---------------- neighbor aggregation: agg[i] = 0.25 * sum_k srcnorm[j]*h[j] ----------
__global__ void agg_kernel(const float* __restrict__ xin, int srcSel, int dstSel,
                           int F, int N) {
    const float* src = (srcSel < 0) ? xin : bufptr(srcSel);
    float* dst = bufptr(dstSel);
    int tpr = F >> 2;
    int rpb = blockDim.x / tpr;
    int r = threadIdx.x / tpr;
    int c = threadIdx.x % tpr;
    int node = blockIdx.x * rpb + r;
    if (node >= N) return;
    const float4* s4 = (const float4*)src;
    float4 acc = make_float4(0.f, 0.f, 0.f, 0.f);
    const int* ip = &g_idx[node * KNN];
#pragma unroll
    for (int k = 0; k < KNN; k++) {
        int j = __ldg(&ip[k]);
        float s = __ldg(&g_srcnorm[j]);
        float4 v = s4[j * tpr + c];
        acc.x = fmaf(s, v.x, acc.x);
        acc.y = fmaf(s, v.y, acc.y);
        acc.z = fmaf(s, v.z, acc.z);
        acc.w = fmaf(s, v.w, acc.w);
    }
    const float dn = 0.25f;
    ((float4*)dst)[node * tpr + c] =
        make_float4(acc.x * dn, acc.y * dn, acc.z * dn, acc.w * dn);
}

// ---------------- fp32 tiled GEMM (packed f32x2 FFMA) + bias + relu --------------------
// BM=128, BN=128, BK=16, 256 threads, 8x8 micro-tile as 8x4 f32x2 pairs  (R8-proven)
__global__ void gemm_kernel(int srcSel, const float* __restrict__ W,
                            const float* __restrict__ bias, int dstSel,
                            int M, int Kd) {
    const float* A = bufptr(srcSel);
    float* C = bufptr(dstSel);
    __shared__ float As[16][132];
    __shared__ float Bs[16][128];
    int tid = threadIdx.x;
    int tx = tid & 15;
    int ty = tid >> 4;
    int bm0 = blockIdx.x * 128;
    int bn0 = blockIdx.y * 128;

    u64 acc2[8][4];
#pragma unroll
    for (int i = 0; i < 8; i++)
#pragma unroll
        for (int j = 0; j < 4; j++) acc2[i][j] = 0ull;

    int ktiles = Kd >> 4;
    for (int kt = 0; kt < ktiles; kt++) {
#pragma unroll
        for (int l = 0; l < 2; l++) {
            int lin = tid + l * 256;
            int arow = lin >> 2;
            int kq = (lin & 3) << 2;
            int grow = bm0 + arow;
            float4 v = make_float4(0.f, 0.f, 0.f, 0.f);
            if (grow < M) v = *(const float4*)&A[grow * Kd + kt * 16 + kq];
            As[kq + 0][arow] = v.x;
            As[kq + 1][arow] = v.y;
            As[kq + 2][arow] = v.z;
            As[kq + 3][arow] = v.w;
        }
#pragma unroll
        for (int l = 0; l < 2; l++) {
            int lin = tid + l * 256;
            int brow = lin >> 5;
            int bc = (lin & 31) << 2;
            float4 v = *(const float4*)&W[(kt * 16 + brow) * HDIM + bn0 + bc];
            *(float4*)&Bs[brow][bc] = v;
        }
        __syncthreads();
#pragma unroll
        for (int kk = 0; kk < 16; kk++) {
            float4 a0 = *(const float4*)&As[kk][ty * 8];
            float4 a1 = *(const float4*)&As[kk][ty * 8 + 4];
            ulonglong2 bp01 = *(const ulonglong2*)&Bs[kk][tx * 8];
            ulonglong2 bp23 = *(const ulonglong2*)&Bs[kk][tx * 8 + 4];
            u64 bp[4] = {bp01.x, bp01.y, bp23.x, bp23.y};
            float a[8] = {a0.x, a0.y, a0.z, a0.w, a1.x, a1.y, a1.z, a1.w};
#pragma unroll
            for (int i = 0; i < 8; i++) {
                u64 aa;
                PACK2(aa, a[i]);
#pragma unroll
                for (int j = 0; j < 4; j++)
                    FMA2(acc2[i][j], aa, bp[j], acc2[i][j]);
            }
        }
        __syncthreads();
    }

    float bb[8];
#pragma unroll
    for (int j = 0; j < 8; j++) bb[j] = __ldg(&bias[bn0 + tx * 8 + j]);
#pragma unroll
    for (int i = 0; i < 8; i++) {
        int row = bm0 + ty * 8 + i;
        if (row < M) {
            float o[8];
#pragma unroll
            for (int j = 0; j < 4; j++) {
                unsigned int lo, hi;
                UNPACK2(lo, hi, acc2[i][j]);
                o[2 * j + 0] = fmaxf(__uint_as_float(lo) + bb[2 * j + 0], 0.f);
                o[2 * j + 1] = fmaxf(__uint_as_float(hi) + bb[2 * j + 1], 0.f);
            }
            *(float4*)&C[row * HDIM + bn0 + tx * 8 + 0] = make_float4(o[0], o[1], o[2], o[3]);
            *(float4*)&C[row * HDIM + bn0 + tx * 8 + 4] = make_float4(o[4], o[5], o[6], o[7]);
        }
    }
}

// ---------------- final: sigmoid(h @ Wf + bf), one warp per row ----------------
__global__ void final_kernel(int srcSel, const float* __restrict__ Wf,
                             const float* __restrict__ bf,
                             float* __restrict__ out, int N) {
    __shared__ float sw[HDIM];
    const float* h = bufptr(srcSel);
    for (int i = threadIdx.x; i < HDIM; i += blockDim.x) sw[i] = Wf[i];
    __syncthreads();
    int warp = threadIdx.x >> 5;
    int lane = threadIdx.x & 31;
    int row = blockIdx.x * 8 + warp;
    if (row >= N) return;
    const float4* h4 = (const float4*)&h[row * HDIM];
    float4 v0 = h4[lane * 2 + 0];
    float4 v1 = h4[lane * 2 + 1];
    float4 w0 = *(const float4*)&sw[lane * 8 + 0];
    float4 w1 = *(const float4*)&sw[lane * 8 + 4];
    float s = v0.x * w0.x + v0.y * w0.y + v0.z * w0.z + v0.w * w0.w
            + v1.x * w1.x + v1.y * w1.y + v1.z * w1.z + v1.w * w1.w;
#pragma unroll
    for (int o = 16; o > 0; o >>= 1) s += __shfl_xor_sync(0xffffffffu, s, o);
    if (lane == 0) {
        float z = s + bf[0];
        out[row] = 1.f / (1.f + expf(-z));
    }
}

// ---------------- launch ----------------
extern "C" void kernel_launch(void* const* d_in, const int* in_sizes, int n_in,
                              void* d_out, int out_size) {
    const float* x       = (const float*)d_in[0];
    const float* centers = (const float*)d_in[1];
    const float* W0      = (const float*)d_in[2];
    const float* b0      = (const float*)d_in[3];
    const float* W1      = (const float*)d_in[4];
    const float* b1      = (const float*)d_in[5];
    const float* W2      = (const float*)d_in[6];
    const float* b2      = (const float*)d_in[7];
    const float* Wf      = (const float*)d_in[8];
    const float* bf      = (const float*)d_in[9];
    float* out = (float*)d_out;

    int N = in_sizes[1] / 3;           // 20000
    int D = in_sizes[0] / N;           // 128

    pack_kernel<<<(N + 255) / 256, 256>>>(centers, N);
    {
        dim3 tg((N + 127) / 128, 2);
        knn_thresh_kernel<<<tg, 128>>>(N);
    }
    thr_merge_kernel<<<(N + 255) / 256, 256>>>(N);
    {
        int half = (N + 1) / 2;
        dim3 kg((half + 127) / 128, CSPB);
        knn_filter_kernel<<<kg, 128>>>(N);
    }
    knn_select_kernel<<<(N + 31) / 32, 128>>>(N);
    norm_kernel<<<(N + 255) / 256, 256>>>(N);

    dim3 gg((N + 127) / 128, HDIM / 128);

    {
        int tpr = D / 4, rpb = 256 / tpr;
        agg_kernel<<<(N + rpb - 1) / rpb, 256>>>(x, -1, 0, D, N);
    }
    gemm_kernel<<<gg, 256>>>(0, W0, b0, 1, N, D);

    {
        int tpr = HDIM / 4, rpb = 256 / tpr;
        agg_kernel<<<(N + rpb - 1) / rpb, 256>>>(nullptr, 1, 0, HDIM, N);
    }
    gemm_kernel<<<gg, 256>>>(0, W1, b1, 2, N, HDIM);

    {
        int tpr = HDIM / 4, rpb = 256 / tpr;
        agg_kernel<<<(N + rpb - 1) / rpb, 256>>>(nullptr, 2, 0, HDIM, N);
    }
    gemm_kernel<<<gg, 256>>>(0, W2, b2, 1, N, HDIM);

    final_kernel<<<(N + 7) / 8, 256>>>(1, Wf, bf, out, N);
}